// round 1
// baseline (speedup 1.0000x reference)
#include <cuda_runtime.h>
#include <cstdint>

#define MAX_B   64
#define IDMAX   4096
#define NOTFOUND 0x7FFFFFFF

// Scratch: per-graph id -> first local position table (atomicMin semantics).
__device__ int g_table[MAX_B * IDMAX];

// ---------------------------------------------------------------------------
// Kernel 1: init table + zero the graph_outputs slice of d_out (it's poisoned)
// ---------------------------------------------------------------------------
__global__ void init_kernel(float* __restrict__ graph_out, int graph_elems, int table_elems) {
    int i = blockIdx.x * blockDim.x + threadIdx.x;
    if (i < table_elems) g_table[i] = NOTFOUND;
    if (i < graph_elems) graph_out[i] = 0.0f;
}

// ---------------------------------------------------------------------------
// Kernel 2: build per-graph id -> min(local position) table
// ---------------------------------------------------------------------------
__global__ void build_table_kernel(const int* __restrict__ node_index,
                                   const int* __restrict__ ptr,
                                   int B, int N) {
    int r = blockIdx.x * blockDim.x + threadIdx.x;
    if (r >= N) return;
    int lo_bound = ptr[0];
    int hi_bound = ptr[B];
    if (r < lo_bound || r >= hi_bound) return;   // rows outside segments: dropped
    // binary search: largest b with ptr[b] <= r
    int lo = 0, hi = B - 1;
    while (lo < hi) {
        int mid = (lo + hi + 1) >> 1;
        if (ptr[mid] <= r) lo = mid; else hi = mid - 1;
    }
    int b  = lo;
    int id = node_index[r];
    if (id >= 0 && id < IDMAX) {
        atomicMin(&g_table[b * IDMAX + id], r - ptr[b]);
    }
}

// ---------------------------------------------------------------------------
// Kernel 3: segment sum pooling. grid = (B, CHUNKS), blockDim = D.
// Thread d accumulates column d over its row chunk, then one atomicAdd.
// ---------------------------------------------------------------------------
__global__ void pool_kernel(const float* __restrict__ x,
                            const int* __restrict__ ptr,
                            float* __restrict__ graph_out,
                            int D, int chunks) {
    int b = blockIdx.x;
    int c = blockIdx.y;
    int d = threadIdx.x;
    int s = ptr[b], e = ptr[b + 1];
    int size  = e - s;
    int chunk = (size + chunks - 1) / chunks;
    int r0 = s + c * chunk;
    int r1 = min(e, r0 + chunk);
    if (r0 >= r1) return;
    float acc = 0.0f;
    const float* xp = x + (size_t)r0 * D + d;
    for (int r = r0; r < r1; r++) {
        acc += *xp;
        xp += D;
    }
    atomicAdd(&graph_out[b * D + d], acc);
}

// ---------------------------------------------------------------------------
// Kernel 4: gather. One warp per token (b,l). D=256 fast path: 2x float4/lane.
// ---------------------------------------------------------------------------
__global__ void gather_kernel(const int* __restrict__ input_ids,
                              const float* __restrict__ x,
                              float* __restrict__ seq_out,
                              int L, int D, int total_tokens) {
    int token = blockIdx.x * (blockDim.x >> 5) + (threadIdx.x >> 5);
    if (token >= total_tokens) return;
    int lane = threadIdx.x & 31;
    int b = token / L;
    int t = input_ids[token];
    int pos = g_table[b * IDMAX + t];

    float4* dst = (float4*)(seq_out + (size_t)token * D);
    int nvec = D >> 2;
    if (pos == NOTFOUND) {
        float4 z = make_float4(0.f, 0.f, 0.f, 0.f);
        for (int i = lane; i < nvec; i += 32) dst[i] = z;
    } else {
        const float4* src = (const float4*)(x + (size_t)pos * D);
        for (int i = lane; i < nvec; i += 32) dst[i] = src[i];
    }
}

// ---------------------------------------------------------------------------
extern "C" void kernel_launch(void* const* d_in, const int* in_sizes, int n_in,
                              void* d_out, int out_size) {
    const int*   input_ids  = (const int*)  d_in[0];   // [B, L]
    const int*   node_index = (const int*)  d_in[1];   // [N]
    const float* x          = (const float*)d_in[2];   // [N, D]
    const int*   ptr        = (const int*)  d_in[3];   // [B+1]

    int B = in_sizes[3] - 1;
    int N = in_sizes[1];
    int D = in_sizes[2] / N;
    int L = in_sizes[0] / B;
    int total_tokens = B * L;

    float* seq_out   = (float*)d_out;                        // [B*L, D]
    float* graph_out = (float*)d_out + (size_t)total_tokens * D;  // [B, D]

    // 1) init
    {
        int table_elems = B * IDMAX;
        int graph_elems = B * D;
        int n = max(table_elems, graph_elems);
        init_kernel<<<(n + 255) / 256, 256>>>(graph_out, graph_elems, table_elems);
    }
    // 2) build id->first-local-pos table
    build_table_kernel<<<(N + 255) / 256, 256>>>(node_index, ptr, B, N);
    // 3) pooling
    {
        const int CHUNKS = 16;
        dim3 grid(B, CHUNKS);
        pool_kernel<<<grid, D>>>(x, ptr, graph_out, D, CHUNKS);
    }
    // 4) gather (one warp per token, 8 warps/block)
    {
        int warps_per_block = 8;
        int blocks = (total_tokens + warps_per_block - 1) / warps_per_block;
        gather_kernel<<<blocks, warps_per_block * 32>>>(input_ids, x, seq_out,
                                                        L, D, total_tokens);
    }
}